// round 9
// baseline (speedup 1.0000x reference)
#include <cuda_runtime.h>

#define FULL_MASK 0xFFFFFFFFu

constexpr int BLOCK = 256;
constexpr int ITEMS = 32;                 // per thread, 8x float4
constexpr int TILE  = BLOCK * ITEMS;      // 8192 floats
constexpr int NWARPS = BLOCK / 32;
constexpr int MAX_TILES = 4096;           // 2^25 / 8192
constexpr int PRE = 8;                    // prefetched windows per walk step (256 descriptors)

// Lookback descriptors, epoch-tagged (no clearing pass between graph replays).
// High 32 bits = (epoch << 2) | state, low 32 bits = fp32 bits.
//   state: 0 = invalid, 1 = aggregate, 2 = inclusive.  States are MONOTONIC,
// and an aggregate value stays correct even after the word is upgraded to
// inclusive — so stale snapshots are safe to consume.
__device__ unsigned long long g_status[MAX_TILES];
__device__ unsigned int       g_ticket;   // monotonic across replays, never reset

__device__ __forceinline__ unsigned long long ld_status(const unsigned long long* p) {
    unsigned long long v;
    asm volatile("ld.relaxed.gpu.global.u64 %0, [%1];" : "=l"(v) : "l"(p));
    return v;
}
__device__ __forceinline__ void st_status(unsigned long long* p, unsigned long long v) {
    asm volatile("st.relaxed.gpu.global.u64 [%0], %1;" :: "l"(p), "l"(v) : "memory");
}
__device__ __forceinline__ unsigned long long pack_status(unsigned epoch, unsigned state, float val) {
    return ((unsigned long long)((epoch << 2) | state) << 32)
         | (unsigned long long)__float_as_uint(val);
}

__global__ void __launch_bounds__(BLOCK)
scan_kernel(const float* __restrict__ x, float* __restrict__ out, int n, unsigned ntiles) {
    __shared__ float    s_warp[NWARPS];
    __shared__ float    s_prefix;
    __shared__ unsigned s_ticket;

    const int lane = threadIdx.x & 31;
    const int wid  = threadIdx.x >> 5;

    // Ticket: issued in CTA scheduling order -> predecessors resident/retired.
    if (threadIdx.x == 0) s_ticket = atomicAdd(&g_ticket, 1u);
    __syncthreads();
    const unsigned ticket = s_ticket;
    const unsigned epoch  = ticket / ntiles;
    const unsigned tile   = ticket % ntiles;
    const size_t base = (size_t)tile * TILE + (size_t)threadIdx.x * ITEMS;

    // ---- Load 32 consecutive floats per thread (8x LDG.128) ----
    float v[ITEMS];
    const bool full_tile = (base + ITEMS) <= (size_t)n;
    if (full_tile) {
        const float4* p = reinterpret_cast<const float4*>(x + base);
        #pragma unroll
        for (int j = 0; j < ITEMS / 4; j++) {
            float4 a = p[j];
            v[4*j+0] = a.x; v[4*j+1] = a.y; v[4*j+2] = a.z; v[4*j+3] = a.w;
        }
    } else {
        #pragma unroll
        for (int i = 0; i < ITEMS; i++)
            v[i] = (base + (size_t)i < (size_t)n) ? x[base + i] : 0.f;
    }

    // ---- Thread-serial inclusive scan ----
    #pragma unroll
    for (int i = 1; i < ITEMS; i++) v[i] += v[i - 1];
    const float tsum = v[ITEMS - 1];

    // ---- Warp inclusive scan of thread sums ----
    float incl = tsum;
    #pragma unroll
    for (int d = 1; d < 32; d <<= 1) {
        float t = __shfl_up_sync(FULL_MASK, incl, d);
        if (lane >= d) incl += t;
    }
    const float texcl = incl - tsum;
    if (lane == 31) s_warp[wid] = incl;
    __syncthreads();

    // ---- Warp 0: block scan of warp totals + bulk-prefetch lookback ----
    if (wid == 0) {
        float wv = (lane < NWARPS) ? s_warp[lane] : 0.f;
        float wincl = wv;
        #pragma unroll
        for (int d = 1; d < NWARPS; d <<= 1) {
            float t = __shfl_up_sync(FULL_MASK, wincl, d);
            if (lane >= d) wincl += t;
        }
        const float block_agg = __shfl_sync(FULL_MASK, wincl, NWARPS - 1);
        if (lane < NWARPS) s_warp[lane] = wincl - wv;  // exclusive warp offsets

        float prefix = 0.f;
        if (tile == 0) {
            if (lane == 0) st_status(&g_status[0], pack_status(epoch, 2u, block_agg));
        } else {
            if (lane == 0) st_status(&g_status[tile], pack_status(epoch, 1u, block_agg));

            int wend = (int)tile;            // descriptors (wend-1-offset), offset ascending = farther back
            bool done = false;
            while (!done) {
                // Bulk snapshot: PRE windows = PRE*32 descriptors, PRE independent
                // loads per lane -> ONE L2 round trip for the expected whole walk.
                unsigned stj[PRE]; float vj[PRE];
                #pragma unroll
                for (int j = 0; j < PRE; j++) {
                    int idx = wend - 1 - (j * 32 + lane);
                    if (idx >= 0) {
                        unsigned long long w = ld_status(&g_status[idx]);
                        unsigned tg = (unsigned)(w >> 32);
                        stj[j] = ((tg >> 2) == epoch) ? (tg & 3u) : 0u;
                        vj[j]  = __uint_as_float((unsigned)(w & 0xFFFFFFFFull));
                    } else { stj[j] = 2u; vj[j] = 0.f; }
                }
                // Consume windows nearest-first.
                #pragma unroll
                for (int j = 0; j < PRE; j++) {
                    if (done) break;
                    // Repoll only if this window still has invalid entries.
                    while (__any_sync(FULL_MASK, stj[j] == 0u)) {
                        int idx = wend - 1 - (j * 32 + lane);
                        if (idx >= 0) {
                            unsigned long long w = ld_status(&g_status[idx]);
                            unsigned tg = (unsigned)(w >> 32);
                            stj[j] = ((tg >> 2) == epoch) ? (tg & 3u) : 0u;
                            vj[j]  = __uint_as_float((unsigned)(w & 0xFFFFFFFFull));
                        } else { stj[j] = 2u; vj[j] = 0.f; }
                    }
                    unsigned bal = __ballot_sync(FULL_MASK, stj[j] == 2u);
                    float c;
                    if (bal) {
                        int b = __ffs(bal) - 1;        // nearest INCLUSIVE (smallest offset)
                        c = (lane <= b) ? vj[j] : 0.f; // aggregates below + inclusive at b
                        done = true;
                    } else {
                        c = vj[j];                     // all aggregates: consume window
                    }
                    #pragma unroll
                    for (int o = 16; o > 0; o >>= 1)
                        c += __shfl_xor_sync(FULL_MASK, c, o);
                    prefix += c;
                }
                wend -= PRE * 32;
            }
            if (lane == 0)
                st_status(&g_status[tile], pack_status(epoch, 2u, prefix + block_agg));
        }
        if (lane == 0) s_prefix = prefix;
    }
    __syncthreads();

    // ---- Apply offsets and store (8x STG.128) ----
    const float off = s_prefix + s_warp[wid] + texcl;
    #pragma unroll
    for (int i = 0; i < ITEMS; i++) v[i] += off;

    if (full_tile) {
        float4* q = reinterpret_cast<float4*>(out + base);
        #pragma unroll
        for (int j = 0; j < ITEMS / 4; j++)
            q[j] = make_float4(v[4*j+0], v[4*j+1], v[4*j+2], v[4*j+3]);
    } else {
        #pragma unroll
        for (int i = 0; i < ITEMS; i++)
            if (base + (size_t)i < (size_t)n) out[base + i] = v[i];
    }
}

extern "C" void kernel_launch(void* const* d_in, const int* in_sizes, int n_in,
                              void* d_out, int out_size) {
    const float* x = (const float*)d_in[0];
    float* out = (float*)d_out;
    int n = in_sizes[0];
    unsigned ntiles = (unsigned)((n + TILE - 1) / TILE);
    if (ntiles > MAX_TILES) ntiles = MAX_TILES;  // sized for the fixed N=2^25 problem

    scan_kernel<<<ntiles, BLOCK>>>(x, out, n, ntiles);
}